// round 2
// baseline (speedup 1.0000x reference)
#include <cuda_runtime.h>
#include <cuda_bf16.h>

// Problem constants (GNN_Attention: N=50000, E=800000, IN=8, ED=2, H=2, C=64,
// HID=64, OUT=2). Capacities for static scratch:
#define MAXN 50000
#define MAXE 800000
#define HC   128      // H*C
#define HID  64
#define NEG_SLOPE 0.2f

// -------- static device scratch (no allocation allowed) --------
// 16B alignment is required for float4 loads / red.global.add.v4.f32 targets.
__device__ __align__(16) float g_xl[MAXN * HC];     // source projection  [N,128]
__device__ __align__(16) float g_xr[MAXN * HC];     // target projection  [N,128]
__device__ __align__(16) float g_expl[MAXE * 2];    // exp(logit) per edge,head
__device__ __align__(16) float g_ew[MAXE];          // mean-head alpha per edge
__device__ __align__(16) float g_denom[MAXN * 2];   // softmax denominator per node,head
__device__ __align__(16) float g_deg[MAXN];         // gcn degree (sum of ew at dst)
__device__ __align__(16) float g_dinv[MAXN];        // rsqrt(deg) or 0
__device__ __align__(16) float g_hacc[MAXN * HC];   // GAT message accumulator
__device__ __align__(16) float g_hw[MAXN * HID];    // relu(h) @ gcn_W.T
__device__ __align__(16) float g_h2acc[MAXN * HID]; // GCN accumulator

// vectorized reduction (no-return atomic add), sm_90+
__device__ __forceinline__ void red_add_v4(float* p, float4 v) {
    asm volatile("red.global.add.v4.f32 [%0], {%1,%2,%3,%4};"
                 :: "l"(p), "f"(v.x), "f"(v.y), "f"(v.z), "f"(v.w)
                 : "memory");
}

// -------- 1. zero accumulators (graph replays reuse scratch) --------
__global__ void k_zero(int N) {
    int i = blockIdx.x * blockDim.x + threadIdx.x;
    if (i < N * HC)  g_hacc[i]  = 0.f;
    if (i < N * HID) g_h2acc[i] = 0.f;
    if (i < N * 2)   g_denom[i] = 0.f;
    if (i < N)       g_deg[i]   = 0.f;
}

// -------- 2. node projections: xl = x@Wl.T+bl, xr = x@Wr.T+br --------
__global__ void k_proj(const float* __restrict__ x,
                       const float* __restrict__ Wl, const float* __restrict__ bl,
                       const float* __restrict__ Wr, const float* __restrict__ br,
                       int N) {
    int idx = blockIdx.x * blockDim.x + threadIdx.x;
    if (idx >= N * HC) return;
    int n = idx >> 7, ch = idx & 127;
    const float* xv = x + n * 8;
    float sl = bl[ch], sr = br[ch];
    #pragma unroll
    for (int i = 0; i < 8; i++) {
        float xi = xv[i];
        sl += xi * Wl[ch * 8 + i];
        sr += xi * Wr[ch * 8 + i];
    }
    g_xl[idx] = sl;
    g_xr[idx] = sr;
}

// -------- 3. per-edge attention logits + exp + denom (warp/edge) --------
// NOTE: edge_index is int32 (JAX default x64-disabled downcasts int64).
__global__ void k_logits(const int* __restrict__ ei,
                         const float* __restrict__ ea,
                         const float* __restrict__ We,
                         const float* __restrict__ att, int E) {
    int t = blockIdx.x * blockDim.x + threadIdx.x;
    int e = t >> 5;
    if (e >= E) return;
    int lane = t & 31;
    int src = ei[e];
    int dst = ei[E + e];

    float4 a = ((const float4*)g_xl)[src * 32 + lane];
    float4 b = ((const float4*)g_xr)[dst * 32 + lane];
    float ea0 = __ldg(ea + 2 * e), ea1 = __ldg(ea + 2 * e + 1);

    // edge projection for this lane's 4 channels (We is [128,2] row-major)
    float4 we01 = ((const float4*)We)[2 * lane];
    float4 we23 = ((const float4*)We)[2 * lane + 1];
    float e0 = we01.x * ea0 + we01.y * ea1;
    float e1 = we01.z * ea0 + we01.w * ea1;
    float e2 = we23.x * ea0 + we23.y * ea1;
    float e3 = we23.z * ea0 + we23.w * ea1;

    float4 at = ((const float4*)att)[lane];   // att flat over 128 channels

    float z, s = 0.f;
    z = a.x + b.x + e0; z = z > 0.f ? z : NEG_SLOPE * z; s += z * at.x;
    z = a.y + b.y + e1; z = z > 0.f ? z : NEG_SLOPE * z; s += z * at.y;
    z = a.z + b.z + e2; z = z > 0.f ? z : NEG_SLOPE * z; s += z * at.z;
    z = a.w + b.w + e3; z = z > 0.f ? z : NEG_SLOPE * z; s += z * at.w;

    // reduce within each half-warp (lanes 0-15 -> head0, 16-31 -> head1)
    #pragma unroll
    for (int o = 8; o >= 1; o >>= 1)
        s += __shfl_down_sync(0xffffffffu, s, o, 16);

    if ((lane & 15) == 0) {
        int h = lane >> 4;
        float p = expf(s);   // no max-subtraction needed: |logit| small
        g_expl[2 * e + h] = p;
        atomicAdd(&g_denom[2 * dst + h], p);
    }
}

// -------- 4. alpha, edge weight, GAT message scatter (warp/edge) --------
__global__ void k_alpha_msg(const int* __restrict__ ei,
                            float* __restrict__ alpha_out, int E) {
    int t = blockIdx.x * blockDim.x + threadIdx.x;
    int e = t >> 5;
    if (e >= E) return;
    int lane = t & 31;
    int src = ei[e];
    int dst = ei[E + e];

    float p0 = g_expl[2 * e], p1 = g_expl[2 * e + 1];
    float a0 = p0 / g_denom[2 * dst];
    float a1 = p1 / g_denom[2 * dst + 1];

    if (lane == 0) {
        alpha_out[2 * e]     = a0;
        alpha_out[2 * e + 1] = a1;
        float ewv = 0.5f * (a0 + a1);
        g_ew[e] = ewv;
        atomicAdd(&g_deg[dst], ewv);
    }

    float aa = (lane < 16) ? a0 : a1;
    float4 v = ((const float4*)g_xl)[src * 32 + lane];
    v.x *= aa; v.y *= aa; v.z *= aa; v.w *= aa;
    red_add_v4(&g_hacc[dst * HC + lane * 4], v);
}

// -------- 5. per-node: relu(h)+bias, hw = h@gcn_W.T, dinv --------
__global__ void k_node_hw(const float* __restrict__ gat_bias,
                          const float* __restrict__ gcn_W, int N) {
    int n = blockIdx.x;
    int t = threadIdx.x;                 // 64 threads
    __shared__ __align__(16) float hsh[HC];
    float v0 = g_hacc[n * HC + t]      + gat_bias[t];
    float v1 = g_hacc[n * HC + 64 + t] + gat_bias[64 + t];
    hsh[t]      = fmaxf(v0, 0.f);
    hsh[64 + t] = fmaxf(v1, 0.f);
    if (t == 0) {
        float dg = g_deg[n];
        g_dinv[n] = dg > 0.f ? rsqrtf(dg) : 0.f;
    }
    __syncthreads();
    const float4* W4 = (const float4*)(gcn_W + t * HC);
    const float4* h4 = (const float4*)hsh;
    float acc = 0.f;
    #pragma unroll
    for (int i = 0; i < HC / 4; i++) {
        float4 w = W4[i], hh = h4[i];
        acc += w.x * hh.x + w.y * hh.y + w.z * hh.z + w.w * hh.w;
    }
    g_hw[n * HID + t] = acc;
}

// -------- 6. GCN edge scatter: h2acc[dst] += hw[src]*norm (16 lanes/edge) --------
__global__ void k_gcn_edge(const int* __restrict__ ei, int E) {
    int t = blockIdx.x * blockDim.x + threadIdx.x;
    int e = t >> 4;
    if (e >= E) return;
    int l = t & 15;
    int src = ei[e];
    int dst = ei[E + e];
    float nv = g_dinv[src] * g_ew[e] * g_dinv[dst];
    float4 v = ((const float4*)g_hw)[src * 16 + l];
    v.x *= nv; v.y *= nv; v.z *= nv; v.w *= nv;
    red_add_v4(&g_h2acc[dst * HID + l * 4], v);
}

// -------- 7. per-node output: relu(h2+b) @ out_W.T + out_b (warp/node) --------
__global__ void k_node_out(const float* __restrict__ gcn_b,
                           const float* __restrict__ out_W,
                           const float* __restrict__ out_b,
                           float* __restrict__ out, int N) {
    int t = blockIdx.x * blockDim.x + threadIdx.x;
    int n = t >> 5;
    if (n >= N) return;
    int lane = t & 31;
    float2 hv = ((const float2*)g_h2acc)[n * 32 + lane];
    float h0 = fmaxf(hv.x + gcn_b[2 * lane],     0.f);
    float h1 = fmaxf(hv.y + gcn_b[2 * lane + 1], 0.f);
    float s0 = h0 * out_W[2 * lane]      + h1 * out_W[2 * lane + 1];
    float s1 = h0 * out_W[64 + 2 * lane] + h1 * out_W[64 + 2 * lane + 1];
    #pragma unroll
    for (int o = 16; o >= 1; o >>= 1) {
        s0 += __shfl_down_sync(0xffffffffu, s0, o);
        s1 += __shfl_down_sync(0xffffffffu, s1, o);
    }
    if (lane == 0) {
        out[2 * n]     = s0 + out_b[0];
        out[2 * n + 1] = s1 + out_b[1];
    }
}

extern "C" void kernel_launch(void* const* d_in, const int* in_sizes, int n_in,
                              void* d_out, int out_size) {
    const float* x        = (const float*)d_in[0];
    const float* ea       = (const float*)d_in[1];
    const int*   ei       = (const int*)d_in[2];   // int32! (JAX x64 disabled)
    const float* Wl       = (const float*)d_in[3];
    const float* bl       = (const float*)d_in[4];
    const float* Wr       = (const float*)d_in[5];
    const float* br       = (const float*)d_in[6];
    const float* We       = (const float*)d_in[7];
    const float* att      = (const float*)d_in[8];
    const float* gat_bias = (const float*)d_in[9];
    const float* gcn_W    = (const float*)d_in[10];
    const float* gcn_b    = (const float*)d_in[11];
    const float* out_W    = (const float*)d_in[12];
    const float* out_b    = (const float*)d_in[13];

    int N = in_sizes[0] / 8;     // IN=8
    int E = in_sizes[1] / 2;     // ED=2

    float* out       = (float*)d_out;
    float* alpha_out = (float*)d_out + (size_t)N * 2;   // (out, alpha) concatenated

    const int NT = 256;
    k_zero<<<(N * HC + NT - 1) / NT, NT>>>(N);
    k_proj<<<(N * HC + NT - 1) / NT, NT>>>(x, Wl, bl, Wr, br, N);
    k_logits<<<(int)(((size_t)E * 32 + NT - 1) / NT), NT>>>(ei, ea, We, att, E);
    k_alpha_msg<<<(int)(((size_t)E * 32 + NT - 1) / NT), NT>>>(ei, alpha_out, E);
    k_node_hw<<<N, 64>>>(gat_bias, gcn_W, N);
    k_gcn_edge<<<(int)(((size_t)E * 16 + NT - 1) / NT), NT>>>(ei, E);
    k_node_out<<<(int)(((size_t)N * 32 + NT - 1) / NT), NT>>>(gcn_b, out_W, out_b, out, N);
}

// round 3
// speedup vs baseline: 1.1207x; 1.1207x over previous
#include <cuda_runtime.h>
#include <cuda_bf16.h>

// GNN_Attention: N=50000, E=800000, IN=8, ED=2, H=2, C=64, HID=64, OUT=2
#define MAXN 50000
#define MAXE 800000
#define HC   128
#define HID  64
#define NEG_SLOPE 0.2f

// -------- static device scratch (16B aligned for float4 / red.v4) --------
__device__ __align__(16) float g_xl[MAXN * HC];
__device__ __align__(16) float g_xr[MAXN * HC];
__device__ __align__(16) float g_expl[MAXE * 2];
__device__ __align__(16) float g_ew[MAXE];
__device__ __align__(16) float g_denom[MAXN * 2];
__device__ __align__(16) float g_deg[MAXN];
__device__ __align__(16) float g_dinv[MAXN];
__device__ __align__(16) float g_hacc[MAXN * HC];
__device__ __align__(16) float g_hw[MAXN * HID];
__device__ __align__(16) float g_h2acc[MAXN * HID];

__device__ __forceinline__ void red_add_v4(float* p, float4 v) {
    asm volatile("red.global.add.v4.f32 [%0], {%1,%2,%3,%4};"
                 :: "l"(p), "f"(v.x), "f"(v.y), "f"(v.z), "f"(v.w)
                 : "memory");
}

// -------- 1. zero accumulators --------
__global__ void k_zero(int N) {
    int i = blockIdx.x * blockDim.x + threadIdx.x;
    if (i < N * HC)  g_hacc[i]  = 0.f;
    if (i < N * HID) g_h2acc[i] = 0.f;
    if (i < N * 2)   g_denom[i] = 0.f;
    if (i < N)       g_deg[i]   = 0.f;
}

// -------- 2. node projections --------
__global__ void k_proj(const float* __restrict__ x,
                       const float* __restrict__ Wl, const float* __restrict__ bl,
                       const float* __restrict__ Wr, const float* __restrict__ br,
                       int N) {
    int idx = blockIdx.x * blockDim.x + threadIdx.x;
    if (idx >= N * HC) return;
    int n = idx >> 7, ch = idx & 127;
    const float* xv = x + n * 8;
    float sl = bl[ch], sr = br[ch];
    #pragma unroll
    for (int i = 0; i < 8; i++) {
        float xi = xv[i];
        sl += xi * Wl[ch * 8 + i];
        sr += xi * Wr[ch * 8 + i];
    }
    g_xl[idx] = sl;
    g_xr[idx] = sr;
}

// -------- 3. logits + exp + denom: 4 edges per warp, batched loads --------
__global__ void k_logits(const int* __restrict__ ei,
                         const float* __restrict__ ea,
                         const float* __restrict__ We,
                         const float* __restrict__ att, int E) {
    int warp = (blockIdx.x * blockDim.x + threadIdx.x) >> 5;
    int lane = threadIdx.x & 31;
    int e0 = warp * 4;
    if (e0 >= E) return;

    // per-lane constants
    float4 at   = ((const float4*)att)[lane];
    float4 we01 = ((const float4*)We)[2 * lane];
    float4 we23 = ((const float4*)We)[2 * lane + 1];

    int src[4], dst[4];
    float2 eav[4];
    #pragma unroll
    for (int j = 0; j < 4; j++) {
        int e = min(e0 + j, E - 1);
        src[j] = ei[e];
        dst[j] = ei[E + e];
        eav[j] = ((const float2*)ea)[e];
    }
    // batched gathers (independent -> MLP=8)
    float4 a[4], b[4];
    #pragma unroll
    for (int j = 0; j < 4; j++) a[j] = ((const float4*)g_xl)[src[j] * 32 + lane];
    #pragma unroll
    for (int j = 0; j < 4; j++) b[j] = ((const float4*)g_xr)[dst[j] * 32 + lane];

    float s[4];
    #pragma unroll
    for (int j = 0; j < 4; j++) {
        float e_0 = we01.x * eav[j].x + we01.y * eav[j].y;
        float e_1 = we01.z * eav[j].x + we01.w * eav[j].y;
        float e_2 = we23.x * eav[j].x + we23.y * eav[j].y;
        float e_3 = we23.z * eav[j].x + we23.w * eav[j].y;
        float z, acc = 0.f;
        z = a[j].x + b[j].x + e_0; z = z > 0.f ? z : NEG_SLOPE * z; acc += z * at.x;
        z = a[j].y + b[j].y + e_1; z = z > 0.f ? z : NEG_SLOPE * z; acc += z * at.y;
        z = a[j].z + b[j].z + e_2; z = z > 0.f ? z : NEG_SLOPE * z; acc += z * at.z;
        z = a[j].w + b[j].w + e_3; z = z > 0.f ? z : NEG_SLOPE * z; acc += z * at.w;
        s[j] = acc;
    }
    // reduce within half-warps (lanes 0-15: head0, 16-31: head1)
    #pragma unroll
    for (int o = 8; o >= 1; o >>= 1) {
        #pragma unroll
        for (int j = 0; j < 4; j++)
            s[j] += __shfl_down_sync(0xffffffffu, s[j], o, 16);
    }
    if ((lane & 15) == 0) {
        int h = lane >> 4;
        #pragma unroll
        for (int j = 0; j < 4; j++) {
            int e = e0 + j;
            if (e < E) {
                float p = __expf(s[j]);
                g_expl[2 * e + h] = p;
                atomicAdd(&g_denom[2 * dst[j] + h], p);
            }
        }
    }
}

// -------- 4. alpha + ew/deg + GAT message scatter: 4 edges per warp --------
__global__ void k_alpha_msg(const int* __restrict__ ei,
                            float* __restrict__ alpha_out, int E) {
    int warp = (blockIdx.x * blockDim.x + threadIdx.x) >> 5;
    int lane = threadIdx.x & 31;
    int e0 = warp * 4;
    if (e0 >= E) return;

    int src[4], dst[4];
    #pragma unroll
    for (int j = 0; j < 4; j++) {
        int e = min(e0 + j, E - 1);
        src[j] = ei[e];
        dst[j] = ei[E + e];
    }
    float2 p[4], dn[4];
    #pragma unroll
    for (int j = 0; j < 4; j++) p[j]  = ((const float2*)g_expl)[min(e0 + j, E - 1)];
    #pragma unroll
    for (int j = 0; j < 4; j++) dn[j] = ((const float2*)g_denom)[dst[j]];
    float4 v[4];
    #pragma unroll
    for (int j = 0; j < 4; j++) v[j] = ((const float4*)g_xl)[src[j] * 32 + lane];

    float a0[4], a1[4];
    #pragma unroll
    for (int j = 0; j < 4; j++) {
        a0[j] = __fdividef(p[j].x, dn[j].x);
        a1[j] = __fdividef(p[j].y, dn[j].y);
    }
    // lanes 0-3 each own one edge's scalar outputs
    if (lane < 4) {
        int e = e0 + lane;
        if (e < E) {
            ((float2*)alpha_out)[e] = make_float2(a0[lane], a1[lane]);
            float ewv = 0.5f * (a0[lane] + a1[lane]);
            g_ew[e] = ewv;
            atomicAdd(&g_deg[dst[lane]], ewv);
        }
    }
    #pragma unroll
    for (int j = 0; j < 4; j++) {
        if (e0 + j < E) {
            float aa = (lane < 16) ? a0[j] : a1[j];
            float4 m = v[j];
            m.x *= aa; m.y *= aa; m.z *= aa; m.w *= aa;
            red_add_v4(&g_hacc[dst[j] * HC + lane * 4], m);
        }
    }
}

// -------- 5. per-node: relu(h)+bias, hw = h@gcn_W.T, dinv --------
__global__ void k_node_hw(const float* __restrict__ gat_bias,
                          const float* __restrict__ gcn_W, int N) {
    int n = blockIdx.x;
    int t = threadIdx.x;                 // 64 threads
    __shared__ __align__(16) float hsh[HC];
    float v0 = g_hacc[n * HC + t]      + gat_bias[t];
    float v1 = g_hacc[n * HC + 64 + t] + gat_bias[64 + t];
    hsh[t]      = fmaxf(v0, 0.f);
    hsh[64 + t] = fmaxf(v1, 0.f);
    if (t == 0) {
        float dg = g_deg[n];
        g_dinv[n] = dg > 0.f ? rsqrtf(dg) : 0.f;
    }
    __syncthreads();
    const float4* W4 = (const float4*)(gcn_W + t * HC);
    const float4* h4 = (const float4*)hsh;
    float acc = 0.f;
    #pragma unroll
    for (int i = 0; i < HC / 4; i++) {
        float4 w = W4[i], hh = h4[i];
        acc += w.x * hh.x + w.y * hh.y + w.z * hh.z + w.w * hh.w;
    }
    g_hw[n * HID + t] = acc;
}

// -------- 6. GCN edge scatter: 16 lanes/edge, 8 edges per warp --------
__global__ void k_gcn_edge(const int* __restrict__ ei, int E) {
    int warp = (blockIdx.x * blockDim.x + threadIdx.x) >> 5;
    int lane = threadIdx.x & 31;
    int half = lane >> 4;       // which edge of the pair
    int l    = lane & 15;       // lane within edge (float4 index)
    int e0 = warp * 8 + half;   // edges e0, e0+2, e0+4, e0+6
    if (e0 >= E) return;

    int src[4], dst[4];
    float nv[4];
    #pragma unroll
    for (int j = 0; j < 4; j++) {
        int e = min(e0 + 2 * j, E - 1);
        src[j] = ei[e];
        dst[j] = ei[E + e];
        nv[j]  = g_ew[e];
    }
    #pragma unroll
    for (int j = 0; j < 4; j++)
        nv[j] *= g_dinv[src[j]] * g_dinv[dst[j]];
    float4 v[4];
    #pragma unroll
    for (int j = 0; j < 4; j++)
        v[j] = ((const float4*)g_hw)[src[j] * 16 + l];
    #pragma unroll
    for (int j = 0; j < 4; j++) {
        if (e0 + 2 * j < E) {
            float4 m = v[j];
            m.x *= nv[j]; m.y *= nv[j]; m.z *= nv[j]; m.w *= nv[j];
            red_add_v4(&g_h2acc[dst[j] * HID + l * 4], m);
        }
    }
}

// -------- 7. per-node output --------
__global__ void k_node_out(const float* __restrict__ gcn_b,
                           const float* __restrict__ out_W,
                           const float* __restrict__ out_b,
                           float* __restrict__ out, int N) {
    int t = blockIdx.x * blockDim.x + threadIdx.x;
    int n = t >> 5;
    if (n >= N) return;
    int lane = t & 31;
    float2 hv = ((const float2*)g_h2acc)[n * 32 + lane];
    float h0 = fmaxf(hv.x + gcn_b[2 * lane],     0.f);
    float h1 = fmaxf(hv.y + gcn_b[2 * lane + 1], 0.f);
    float s0 = h0 * out_W[2 * lane]      + h1 * out_W[2 * lane + 1];
    float s1 = h0 * out_W[64 + 2 * lane] + h1 * out_W[64 + 2 * lane + 1];
    #pragma unroll
    for (int o = 16; o >= 1; o >>= 1) {
        s0 += __shfl_down_sync(0xffffffffu, s0, o);
        s1 += __shfl_down_sync(0xffffffffu, s1, o);
    }
    if (lane == 0) {
        out[2 * n]     = s0 + out_b[0];
        out[2 * n + 1] = s1 + out_b[1];
    }
}

extern "C" void kernel_launch(void* const* d_in, const int* in_sizes, int n_in,
                              void* d_out, int out_size) {
    const float* x        = (const float*)d_in[0];
    const float* ea       = (const float*)d_in[1];
    const int*   ei       = (const int*)d_in[2];   // int32 (JAX x64 disabled)
    const float* Wl       = (const float*)d_in[3];
    const float* bl       = (const float*)d_in[4];
    const float* Wr       = (const float*)d_in[5];
    const float* br       = (const float*)d_in[6];
    const float* We       = (const float*)d_in[7];
    const float* att      = (const float*)d_in[8];
    const float* gat_bias = (const float*)d_in[9];
    const float* gcn_W    = (const float*)d_in[10];
    const float* gcn_b    = (const float*)d_in[11];
    const float* out_W    = (const float*)d_in[12];
    const float* out_b    = (const float*)d_in[13];

    int N = in_sizes[0] / 8;     // IN=8
    int E = in_sizes[1] / 2;     // ED=2

    float* out       = (float*)d_out;
    float* alpha_out = (float*)d_out + (size_t)N * 2;

    const int NT = 256;
    int warpsL = (E + 3) / 4;   // 4 edges/warp
    int warpsG = (E + 7) / 8;   // 8 edges/warp
    k_zero<<<(N * HC + NT - 1) / NT, NT>>>(N);
    k_proj<<<(N * HC + NT - 1) / NT, NT>>>(x, Wl, bl, Wr, br, N);
    k_logits<<<(int)(((size_t)warpsL * 32 + NT - 1) / NT), NT>>>(ei, ea, We, att, E);
    k_alpha_msg<<<(int)(((size_t)warpsL * 32 + NT - 1) / NT), NT>>>(ei, alpha_out, E);
    k_node_hw<<<N, 64>>>(gat_bias, gcn_W, N);
    k_gcn_edge<<<(int)(((size_t)warpsG * 32 + NT - 1) / NT), NT>>>(ei, E);
    k_node_out<<<(int)(((size_t)N * 32 + NT - 1) / NT), NT>>>(gcn_b, out_W, out_b, out, N);
}

// round 4
// speedup vs baseline: 1.2298x; 1.0973x over previous
#include <cuda_runtime.h>
#include <cuda_bf16.h>

// GNN_Attention: N=50000, E=800000, IN=8, ED=2, H=2, C=64, HID=64, OUT=2
#define MAXN 50000
#define MAXE 800000
#define HC   128
#define HID  64
#define NEG_SLOPE 0.2f

// -------- static device scratch (16B aligned for float4 / red.v4) --------
__device__ __align__(16) float g_xl[MAXN * HC];
__device__ __align__(16) float g_xr[MAXN * HC];
__device__ __align__(16) float g_expl[MAXE * 2];
__device__ __align__(16) float g_ew[MAXE];
__device__ __align__(16) float g_denom[MAXN * 2];
__device__ __align__(16) float g_deg[MAXN];
__device__ __align__(16) float g_dinv[MAXN];
__device__ __align__(16) float g_hacc[MAXN * HC];   // Σ p·xl[src]  (unnormalized!)
__device__ __align__(16) float g_hw[MAXN * HID];
__device__ __align__(16) float g_h2acc[MAXN * HID];

__device__ __forceinline__ void red_add_v4(float* p, float4 v) {
    asm volatile("red.global.add.v4.f32 [%0], {%1,%2,%3,%4};"
                 :: "l"(p), "f"(v.x), "f"(v.y), "f"(v.z), "f"(v.w)
                 : "memory");
}

// -------- 1. node projections + zero all accumulators (fused) --------
__global__ void k_proj(const float* __restrict__ x,
                       const float* __restrict__ Wl, const float* __restrict__ bl,
                       const float* __restrict__ Wr, const float* __restrict__ br,
                       int N) {
    int idx = blockIdx.x * blockDim.x + threadIdx.x;
    if (idx >= N * HC) return;
    // zeroing folded in (grid covers N*HC >= all accumulator extents)
    g_hacc[idx] = 0.f;
    if (idx < N * HID) g_h2acc[idx] = 0.f;
    if (idx < N * 2)   g_denom[idx] = 0.f;
    if (idx < N)       g_deg[idx]   = 0.f;

    int n = idx >> 7, ch = idx & 127;
    const float* xv = x + n * 8;
    float sl = bl[ch], sr = br[ch];
    #pragma unroll
    for (int i = 0; i < 8; i++) {
        float xi = xv[i];
        sl += xi * Wl[ch * 8 + i];
        sr += xi * Wr[ch * 8 + i];
    }
    g_xl[idx] = sl;
    g_xr[idx] = sr;
}

// -------- 2. fused logits + exp + denom + UNNORMALIZED message scatter --------
// 4 edges per warp; xl[src] stays in registers from logit to message.
__global__ void k_logits(const int* __restrict__ ei,
                         const float* __restrict__ ea,
                         const float* __restrict__ We,
                         const float* __restrict__ att, int E) {
    int warp = (blockIdx.x * blockDim.x + threadIdx.x) >> 5;
    int lane = threadIdx.x & 31;
    int e0 = warp * 4;
    if (e0 >= E) return;

    float4 at   = ((const float4*)att)[lane];
    float4 we01 = ((const float4*)We)[2 * lane];
    float4 we23 = ((const float4*)We)[2 * lane + 1];

    int src[4], dst[4];
    float2 eav[4];
    #pragma unroll
    for (int j = 0; j < 4; j++) {
        int e = min(e0 + j, E - 1);
        src[j] = ei[e];
        dst[j] = ei[E + e];
        eav[j] = ((const float2*)ea)[e];
    }
    float4 a[4], b[4];
    #pragma unroll
    for (int j = 0; j < 4; j++) a[j] = ((const float4*)g_xl)[src[j] * 32 + lane];
    #pragma unroll
    for (int j = 0; j < 4; j++) b[j] = ((const float4*)g_xr)[dst[j] * 32 + lane];

    float s[4];
    #pragma unroll
    for (int j = 0; j < 4; j++) {
        float e_0 = we01.x * eav[j].x + we01.y * eav[j].y;
        float e_1 = we01.z * eav[j].x + we01.w * eav[j].y;
        float e_2 = we23.x * eav[j].x + we23.y * eav[j].y;
        float e_3 = we23.z * eav[j].x + we23.w * eav[j].y;
        float z, acc = 0.f;
        z = a[j].x + b[j].x + e_0; z = z > 0.f ? z : NEG_SLOPE * z; acc += z * at.x;
        z = a[j].y + b[j].y + e_1; z = z > 0.f ? z : NEG_SLOPE * z; acc += z * at.y;
        z = a[j].z + b[j].z + e_2; z = z > 0.f ? z : NEG_SLOPE * z; acc += z * at.z;
        z = a[j].w + b[j].w + e_3; z = z > 0.f ? z : NEG_SLOPE * z; acc += z * at.w;
        s[j] = acc;
    }
    // butterfly reduce within each 16-lane half -> every lane holds its head's sum
    #pragma unroll
    for (int o = 8; o >= 1; o >>= 1) {
        #pragma unroll
        for (int j = 0; j < 4; j++)
            s[j] += __shfl_xor_sync(0xffffffffu, s[j], o, 16);
    }
    float p[4];
    #pragma unroll
    for (int j = 0; j < 4; j++) p[j] = __expf(s[j]);  // |logit| small: no max-sub

    if ((lane & 15) == 0) {
        int h = lane >> 4;
        #pragma unroll
        for (int j = 0; j < 4; j++) {
            int e = e0 + j;
            if (e < E) {
                g_expl[2 * e + h] = p[j];
                atomicAdd(&g_denom[2 * dst[j] + h], p[j]);
            }
        }
    }
    // unnormalized message: hacc[dst] += p * xl[src]   (xl already in regs)
    #pragma unroll
    for (int j = 0; j < 4; j++) {
        if (e0 + j < E) {
            float4 m = a[j];
            m.x *= p[j]; m.y *= p[j]; m.z *= p[j]; m.w *= p[j];
            red_add_v4(&g_hacc[dst[j] * HC + lane * 4], m);
        }
    }
}

// -------- 3. light alpha pass: alpha, ew, deg (2 edges per thread) --------
__global__ void k_alpha(const int* __restrict__ ei,
                        float* __restrict__ alpha_out, int E) {
    int t = blockIdx.x * blockDim.x + threadIdx.x;
    int e0 = t * 2;
    if (e0 >= E) return;
    int e1 = min(e0 + 1, E - 1);
    int dst0 = ei[E + e0], dst1 = ei[E + e1];
    float2 p0 = ((const float2*)g_expl)[e0];
    float2 p1 = ((const float2*)g_expl)[e1];
    float2 d0 = ((const float2*)g_denom)[dst0];
    float2 d1 = ((const float2*)g_denom)[dst1];
    float a00 = __fdividef(p0.x, d0.x), a01 = __fdividef(p0.y, d0.y);
    float a10 = __fdividef(p1.x, d1.x), a11 = __fdividef(p1.y, d1.y);
    ((float2*)alpha_out)[e0] = make_float2(a00, a01);
    float ew0 = 0.5f * (a00 + a01);
    g_ew[e0] = ew0;
    atomicAdd(&g_deg[dst0], ew0);
    if (e0 + 1 < E) {
        ((float2*)alpha_out)[e1] = make_float2(a10, a11);
        float ew1 = 0.5f * (a10 + a11);
        g_ew[e1] = ew1;
        atomicAdd(&g_deg[dst1], ew1);
    }
}

// -------- 4. per-node: normalize hacc, +bias, relu, hw = h@gcn_W.T, dinv ----
__global__ void k_node_hw(const float* __restrict__ gat_bias,
                          const float* __restrict__ gcn_W, int N) {
    int n = blockIdx.x;
    int t = threadIdx.x;                 // 64 threads
    __shared__ __align__(16) float hsh[HC];
    float2 dn = ((const float2*)g_denom)[n];
    float i0 = dn.x > 0.f ? __fdividef(1.f, dn.x) : 0.f;
    float i1 = dn.y > 0.f ? __fdividef(1.f, dn.y) : 0.f;
    float v0 = g_hacc[n * HC + t]      * i0 + gat_bias[t];
    float v1 = g_hacc[n * HC + 64 + t] * i1 + gat_bias[64 + t];
    hsh[t]      = fmaxf(v0, 0.f);
    hsh[64 + t] = fmaxf(v1, 0.f);
    if (t == 0) {
        float dg = g_deg[n];
        g_dinv[n] = dg > 0.f ? rsqrtf(dg) : 0.f;
    }
    __syncthreads();
    const float4* W4 = (const float4*)(gcn_W + t * HC);
    const float4* h4 = (const float4*)hsh;
    float acc = 0.f;
    #pragma unroll
    for (int i = 0; i < HC / 4; i++) {
        float4 w = W4[i], hh = h4[i];
        acc += w.x * hh.x + w.y * hh.y + w.z * hh.z + w.w * hh.w;
    }
    g_hw[n * HID + t] = acc;
}

// -------- 5. GCN edge scatter: 16 lanes/edge, 8 edges per warp --------
__global__ void k_gcn_edge(const int* __restrict__ ei, int E) {
    int warp = (blockIdx.x * blockDim.x + threadIdx.x) >> 5;
    int lane = threadIdx.x & 31;
    int half = lane >> 4;
    int l    = lane & 15;
    int e0 = warp * 8 + half;
    if (e0 >= E) return;

    int src[4], dst[4];
    float nv[4];
    #pragma unroll
    for (int j = 0; j < 4; j++) {
        int e = min(e0 + 2 * j, E - 1);
        src[j] = ei[e];
        dst[j] = ei[E + e];
        nv[j]  = g_ew[e];
    }
    #pragma unroll
    for (int j = 0; j < 4; j++)
        nv[j] *= g_dinv[src[j]] * g_dinv[dst[j]];
    float4 v[4];
    #pragma unroll
    for (int j = 0; j < 4; j++)
        v[j] = ((const float4*)g_hw)[src[j] * 16 + l];
    #pragma unroll
    for (int j = 0; j < 4; j++) {
        if (e0 + 2 * j < E) {
            float4 m = v[j];
            m.x *= nv[j]; m.y *= nv[j]; m.z *= nv[j]; m.w *= nv[j];
            red_add_v4(&g_h2acc[dst[j] * HID + l * 4], m);
        }
    }
}

// -------- 6. per-node output --------
__global__ void k_node_out(const float* __restrict__ gcn_b,
                           const float* __restrict__ out_W,
                           const float* __restrict__ out_b,
                           float* __restrict__ out, int N) {
    int t = blockIdx.x * blockDim.x + threadIdx.x;
    int n = t >> 5;
    if (n >= N) return;
    int lane = t & 31;
    float2 hv = ((const float2*)g_h2acc)[n * 32 + lane];
    float h0 = fmaxf(hv.x + gcn_b[2 * lane],     0.f);
    float h1 = fmaxf(hv.y + gcn_b[2 * lane + 1], 0.f);
    float s0 = h0 * out_W[2 * lane]      + h1 * out_W[2 * lane + 1];
    float s1 = h0 * out_W[64 + 2 * lane] + h1 * out_W[64 + 2 * lane + 1];
    #pragma unroll
    for (int o = 16; o >= 1; o >>= 1) {
        s0 += __shfl_down_sync(0xffffffffu, s0, o);
        s1 += __shfl_down_sync(0xffffffffu, s1, o);
    }
    if (lane == 0) {
        out[2 * n]     = s0 + out_b[0];
        out[2 * n + 1] = s1 + out_b[1];
    }
}

extern "C" void kernel_launch(void* const* d_in, const int* in_sizes, int n_in,
                              void* d_out, int out_size) {
    const float* x        = (const float*)d_in[0];
    const float* ea       = (const float*)d_in[1];
    const int*   ei       = (const int*)d_in[2];   // int32 (JAX x64 disabled)
    const float* Wl       = (const float*)d_in[3];
    const float* bl       = (const float*)d_in[4];
    const float* Wr       = (const float*)d_in[5];
    const float* br       = (const float*)d_in[6];
    const float* We       = (const float*)d_in[7];
    const float* att      = (const float*)d_in[8];
    const float* gat_bias = (const float*)d_in[9];
    const float* gcn_W    = (const float*)d_in[10];
    const float* gcn_b    = (const float*)d_in[11];
    const float* out_W    = (const float*)d_in[12];
    const float* out_b    = (const float*)d_in[13];

    int N = in_sizes[0] / 8;     // IN=8
    int E = in_sizes[1] / 2;     // ED=2

    float* out       = (float*)d_out;
    float* alpha_out = (float*)d_out + (size_t)N * 2;

    const int NT = 256;
    int warpsL = (E + 3) / 4;   // 4 edges/warp
    int warpsG = (E + 7) / 8;   // 8 edges/warp
    k_proj<<<(N * HC + NT - 1) / NT, NT>>>(x, Wl, bl, Wr, br, N);
    k_logits<<<(int)(((size_t)warpsL * 32 + NT - 1) / NT), NT>>>(ei, ea, We, att, E);
    k_alpha<<<(E / 2 + NT - 1) / NT, NT>>>(ei, alpha_out, E);
    k_node_hw<<<N, 64>>>(gat_bias, gcn_W, N);
    k_gcn_edge<<<(int)(((size_t)warpsG * 32 + NT - 1) / NT), NT>>>(ei, E);
    k_node_out<<<(int)(((size_t)N * 32 + NT - 1) / NT), NT>>>(gcn_b, out_W, out_b, out, N);
}

// round 5
// speedup vs baseline: 1.9880x; 1.6166x over previous
#include <cuda_runtime.h>
#include <cuda_bf16.h>

// GNN_Attention: N=50000, E=800000, IN=8, ED=2, H=2, C=64, HID=64, OUT=2
#define MAXN 50000
#define MAXE 800000
#define HC   128
#define HID  64
#define NEG_SLOPE 0.2f

// -------- static device scratch (16B aligned for float4 / red.v4) --------
__device__ __align__(16) float g_xl[MAXN * HC];
__device__ __align__(16) float g_xr[MAXN * HC];
__device__ __align__(16) float g_expl[MAXE * 2];
__device__ __align__(16) float g_ew[MAXE];
__device__ __align__(16) float g_denom[MAXN * 2];
__device__ __align__(16) float g_deg[MAXN];
__device__ __align__(16) float g_dinv[MAXN];
__device__ __align__(16) float g_hacc[MAXN * HC];   // Σ p·xl[src]  (unnormalized)
__device__ __align__(16) float g_hw[MAXN * HID];
__device__ __align__(16) float g_h2acc[MAXN * HID];

__device__ __forceinline__ void red_add_v4(float* p, float4 v) {
    asm volatile("red.global.add.v4.f32 [%0], {%1,%2,%3,%4};"
                 :: "l"(p), "f"(v.x), "f"(v.y), "f"(v.z), "f"(v.w)
                 : "memory");
}

// -------- 1. node projections + zero all accumulators (fused) --------
__global__ void k_proj(const float* __restrict__ x,
                       const float* __restrict__ Wl, const float* __restrict__ bl,
                       const float* __restrict__ Wr, const float* __restrict__ br,
                       int N) {
    int idx = blockIdx.x * blockDim.x + threadIdx.x;
    if (idx >= N * HC) return;
    g_hacc[idx] = 0.f;
    if (idx < N * HID) g_h2acc[idx] = 0.f;
    if (idx < N * 2)   g_denom[idx] = 0.f;
    if (idx < N)       g_deg[idx]   = 0.f;

    int n = idx >> 7, ch = idx & 127;
    const float* xv = x + n * 8;
    float sl = bl[ch], sr = br[ch];
    #pragma unroll
    for (int i = 0; i < 8; i++) {
        float xi = xv[i];
        sl += xi * Wl[ch * 8 + i];
        sr += xi * Wr[ch * 8 + i];
    }
    g_xl[idx] = sl;
    g_xr[idx] = sr;
}

// -------- 2. fused logits + exp + denom + unnormalized message scatter ------
__global__ void k_logits(const int* __restrict__ ei,
                         const float* __restrict__ ea,
                         const float* __restrict__ We,
                         const float* __restrict__ att, int E) {
    int warp = (blockIdx.x * blockDim.x + threadIdx.x) >> 5;
    int lane = threadIdx.x & 31;
    int e0 = warp * 4;
    if (e0 >= E) return;

    float4 at   = ((const float4*)att)[lane];
    float4 we01 = ((const float4*)We)[2 * lane];
    float4 we23 = ((const float4*)We)[2 * lane + 1];

    int src[4], dst[4];
    float2 eav[4];
    #pragma unroll
    for (int j = 0; j < 4; j++) {
        int e = min(e0 + j, E - 1);
        src[j] = ei[e];
        dst[j] = ei[E + e];
        eav[j] = ((const float2*)ea)[e];
    }
    float4 a[4], b[4];
    #pragma unroll
    for (int j = 0; j < 4; j++) a[j] = ((const float4*)g_xl)[src[j] * 32 + lane];
    #pragma unroll
    for (int j = 0; j < 4; j++) b[j] = ((const float4*)g_xr)[dst[j] * 32 + lane];

    float s[4];
    #pragma unroll
    for (int j = 0; j < 4; j++) {
        float e_0 = we01.x * eav[j].x + we01.y * eav[j].y;
        float e_1 = we01.z * eav[j].x + we01.w * eav[j].y;
        float e_2 = we23.x * eav[j].x + we23.y * eav[j].y;
        float e_3 = we23.z * eav[j].x + we23.w * eav[j].y;
        float z, acc = 0.f;
        z = a[j].x + b[j].x + e_0; z = z > 0.f ? z : NEG_SLOPE * z; acc += z * at.x;
        z = a[j].y + b[j].y + e_1; z = z > 0.f ? z : NEG_SLOPE * z; acc += z * at.y;
        z = a[j].z + b[j].z + e_2; z = z > 0.f ? z : NEG_SLOPE * z; acc += z * at.z;
        z = a[j].w + b[j].w + e_3; z = z > 0.f ? z : NEG_SLOPE * z; acc += z * at.w;
        s[j] = acc;
    }
    #pragma unroll
    for (int o = 8; o >= 1; o >>= 1) {
        #pragma unroll
        for (int j = 0; j < 4; j++)
            s[j] += __shfl_xor_sync(0xffffffffu, s[j], o, 16);
    }
    float p[4];
    #pragma unroll
    for (int j = 0; j < 4; j++) p[j] = __expf(s[j]);  // |logit| small: no max-sub

    if ((lane & 15) == 0) {
        int h = lane >> 4;
        #pragma unroll
        for (int j = 0; j < 4; j++) {
            int e = e0 + j;
            if (e < E) {
                g_expl[2 * e + h] = p[j];
                atomicAdd(&g_denom[2 * dst[j] + h], p[j]);
            }
        }
    }
    #pragma unroll
    for (int j = 0; j < 4; j++) {
        if (e0 + j < E) {
            float4 m = a[j];
            m.x *= p[j]; m.y *= p[j]; m.z *= p[j]; m.w *= p[j];
            red_add_v4(&g_hacc[dst[j] * HC + lane * 4], m);
        }
    }
}

// -------- 3. light alpha pass: alpha, ew, deg --------
__global__ void k_alpha(const int* __restrict__ ei,
                        float* __restrict__ alpha_out, int E) {
    int t = blockIdx.x * blockDim.x + threadIdx.x;
    int e0 = t * 2;
    if (e0 >= E) return;
    int e1 = min(e0 + 1, E - 1);
    int dst0 = ei[E + e0], dst1 = ei[E + e1];
    float2 p0 = ((const float2*)g_expl)[e0];
    float2 p1 = ((const float2*)g_expl)[e1];
    float2 d0 = ((const float2*)g_denom)[dst0];
    float2 d1 = ((const float2*)g_denom)[dst1];
    float a00 = __fdividef(p0.x, d0.x), a01 = __fdividef(p0.y, d0.y);
    float a10 = __fdividef(p1.x, d1.x), a11 = __fdividef(p1.y, d1.y);
    ((float2*)alpha_out)[e0] = make_float2(a00, a01);
    float ew0 = 0.5f * (a00 + a01);
    g_ew[e0] = ew0;
    atomicAdd(&g_deg[dst0], ew0);
    if (e0 + 1 < E) {
        ((float2*)alpha_out)[e1] = make_float2(a10, a11);
        float ew1 = 0.5f * (a10 + a11);
        g_ew[e1] = ew1;
        atomicAdd(&g_deg[dst1], ew1);
    }
}

// -------- 4. tiled node GEMV: normalize, bias, relu, h@gcn_W.T, dinv --------
// 256 threads, 32 nodes/block. gcn_W loaded ONCE per block into smem,
// TRANSPOSED so the inner-loop smem reads are conflict-free & coalesced.
#define NH_NODES 32
__global__ void k_node_hw(const float* __restrict__ gat_bias,
                          const float* __restrict__ gcn_W, int N) {
    __shared__ float Wsh[HC * HID];          // [k][col], 32 KB
    __shared__ __align__(16) float hsh[4][HC];
    __shared__ float bsh[HC];
    int t = threadIdx.x;                     // 256

    // coalesced load of gcn_W[c][k], store transposed Wsh[k*64+c]
    for (int i = t; i < HID * HC; i += 256) {
        int c = i >> 7, k = i & 127;
        Wsh[k * HID + c] = gcn_W[i];
    }
    if (t < HC) bsh[t] = gat_bias[t];
    __syncthreads();

    int grp = t >> 6;         // 0..3 (node group)
    int tx  = t & 63;         // output column
    int base = blockIdx.x * NH_NODES;

    for (int it = 0; it < NH_NODES / 4; it++) {
        int n = base + it * 4 + grp;
        bool ok = (n < N);
        if (ok) {
            float2 dn = ((const float2*)g_denom)[n];
            float i0 = dn.x > 0.f ? __fdividef(1.f, dn.x) : 0.f;
            float i1 = dn.y > 0.f ? __fdividef(1.f, dn.y) : 0.f;
            float v0 = g_hacc[n * HC + tx]      * i0 + bsh[tx];
            float v1 = g_hacc[n * HC + 64 + tx] * i1 + bsh[64 + tx];
            hsh[grp][tx]      = fmaxf(v0, 0.f);
            hsh[grp][64 + tx] = fmaxf(v1, 0.f);
            if (tx == 0) {
                float dg = g_deg[n];
                g_dinv[n] = dg > 0.f ? rsqrtf(dg) : 0.f;
            }
        }
        __syncthreads();
        if (ok) {
            float acc = 0.f;
            const float4* h4 = (const float4*)hsh[grp];
            #pragma unroll
            for (int k4 = 0; k4 < HC / 4; k4++) {
                float4 hh = h4[k4];
                int k = k4 * 4;
                acc += hh.x * Wsh[(k    ) * HID + tx];
                acc += hh.y * Wsh[(k + 1) * HID + tx];
                acc += hh.z * Wsh[(k + 2) * HID + tx];
                acc += hh.w * Wsh[(k + 3) * HID + tx];
            }
            g_hw[n * HID + tx] = acc;
        }
        __syncthreads();
    }
}

// -------- 5. GCN edge scatter: 16 lanes/edge, 8 edges per warp --------
__global__ void k_gcn_edge(const int* __restrict__ ei, int E) {
    int warp = (blockIdx.x * blockDim.x + threadIdx.x) >> 5;
    int lane = threadIdx.x & 31;
    int half = lane >> 4;
    int l    = lane & 15;
    int e0 = warp * 8 + half;
    if (e0 >= E) return;

    int src[4], dst[4];
    float nv[4];
    #pragma unroll
    for (int j = 0; j < 4; j++) {
        int e = min(e0 + 2 * j, E - 1);
        src[j] = ei[e];
        dst[j] = ei[E + e];
        nv[j]  = g_ew[e];
    }
    #pragma unroll
    for (int j = 0; j < 4; j++)
        nv[j] *= g_dinv[src[j]] * g_dinv[dst[j]];
    float4 v[4];
    #pragma unroll
    for (int j = 0; j < 4; j++)
        v[j] = ((const float4*)g_hw)[src[j] * 16 + l];
    #pragma unroll
    for (int j = 0; j < 4; j++) {
        if (e0 + 2 * j < E) {
            float4 m = v[j];
            m.x *= nv[j]; m.y *= nv[j]; m.z *= nv[j]; m.w *= nv[j];
            red_add_v4(&g_h2acc[dst[j] * HID + l * 4], m);
        }
    }
}

// -------- 6. per-node output --------
__global__ void k_node_out(const float* __restrict__ gcn_b,
                           const float* __restrict__ out_W,
                           const float* __restrict__ out_b,
                           float* __restrict__ out, int N) {
    int t = blockIdx.x * blockDim.x + threadIdx.x;
    int n = t >> 5;
    if (n >= N) return;
    int lane = t & 31;
    float2 hv = ((const float2*)g_h2acc)[n * 32 + lane];
    float h0 = fmaxf(hv.x + gcn_b[2 * lane],     0.f);
    float h1 = fmaxf(hv.y + gcn_b[2 * lane + 1], 0.f);
    float s0 = h0 * out_W[2 * lane]      + h1 * out_W[2 * lane + 1];
    float s1 = h0 * out_W[64 + 2 * lane] + h1 * out_W[64 + 2 * lane + 1];
    #pragma unroll
    for (int o = 16; o >= 1; o >>= 1) {
        s0 += __shfl_down_sync(0xffffffffu, s0, o);
        s1 += __shfl_down_sync(0xffffffffu, s1, o);
    }
    if (lane == 0) {
        out[2 * n]     = s0 + out_b[0];
        out[2 * n + 1] = s1 + out_b[1];
    }
}

extern "C" void kernel_launch(void* const* d_in, const int* in_sizes, int n_in,
                              void* d_out, int out_size) {
    const float* x        = (const float*)d_in[0];
    const float* ea       = (const float*)d_in[1];
    const int*   ei       = (const int*)d_in[2];   // int32 (JAX x64 disabled)
    const float* Wl       = (const float*)d_in[3];
    const float* bl       = (const float*)d_in[4];
    const float* Wr       = (const float*)d_in[5];
    const float* br       = (const float*)d_in[6];
    const float* We       = (const float*)d_in[7];
    const float* att      = (const float*)d_in[8];
    const float* gat_bias = (const float*)d_in[9];
    const float* gcn_W    = (const float*)d_in[10];
    const float* gcn_b    = (const float*)d_in[11];
    const float* out_W    = (const float*)d_in[12];
    const float* out_b    = (const float*)d_in[13];

    int N = in_sizes[0] / 8;     // IN=8
    int E = in_sizes[1] / 2;     // ED=2

    float* out       = (float*)d_out;
    float* alpha_out = (float*)d_out + (size_t)N * 2;

    const int NT = 256;
    int warpsL = (E + 3) / 4;   // 4 edges/warp
    int warpsG = (E + 7) / 8;   // 8 edges/warp
    k_proj<<<(N * HC + NT - 1) / NT, NT>>>(x, Wl, bl, Wr, br, N);
    k_logits<<<(int)(((size_t)warpsL * 32 + NT - 1) / NT), NT>>>(ei, ea, We, att, E);
    k_alpha<<<(E / 2 + NT - 1) / NT, NT>>>(ei, alpha_out, E);
    k_node_hw<<<(N + NH_NODES - 1) / NH_NODES, 256>>>(gat_bias, gcn_W, N);
    k_gcn_edge<<<(int)(((size_t)warpsG * 32 + NT - 1) / NT), NT>>>(ei, E);
    k_node_out<<<(int)(((size_t)N * 32 + NT - 1) / NT), NT>>>(gcn_b, out_W, out_b, out, N);
}

// round 6
// speedup vs baseline: 2.5299x; 1.2726x over previous
#include <cuda_runtime.h>
#include <cuda_bf16.h>

// GNN_Attention: N=50000, E=800000, IN=8, ED=2, H=2, C=64, HID=64, OUT=2
#define MAXN 50000
#define MAXE 800000
#define HC   128
#define HID  64
#define NEG_SLOPE 0.2f

// -------- static device scratch (16B aligned for float4 / red.v4) --------
__device__ __align__(16) float g_xl[MAXN * HC];
__device__ __align__(16) float g_xr[MAXN * HC];
__device__ __align__(16) float g_expl[MAXE * 2];
__device__ __align__(16) float g_ew[MAXE];
__device__ __align__(16) float g_denom[MAXN * 2];
__device__ __align__(16) float g_deg[MAXN];
__device__ __align__(16) float g_dinv[MAXN];
__device__ __align__(16) float g_hacc[MAXN * HC];   // Σ p·xl[src]  (unnormalized)
__device__ __align__(16) float g_hw[MAXN * HID];
__device__ __align__(16) float g_h2acc[MAXN * HID];

__device__ __forceinline__ void red_add_v4(float* p, float4 v) {
    asm volatile("red.global.add.v4.f32 [%0], {%1,%2,%3,%4};"
                 :: "l"(p), "f"(v.x), "f"(v.y), "f"(v.z), "f"(v.w)
                 : "memory");
}

// -------- 1. node projections + zero all accumulators (fused) --------
__global__ void k_proj(const float* __restrict__ x,
                       const float* __restrict__ Wl, const float* __restrict__ bl,
                       const float* __restrict__ Wr, const float* __restrict__ br,
                       int N) {
    int idx = blockIdx.x * blockDim.x + threadIdx.x;
    if (idx >= N * HC) return;
    g_hacc[idx] = 0.f;
    if (idx < N * HID) g_h2acc[idx] = 0.f;
    if (idx < N * 2)   g_denom[idx] = 0.f;
    if (idx < N)       g_deg[idx]   = 0.f;

    int n = idx >> 7, ch = idx & 127;
    const float* xv = x + n * 8;
    float sl = bl[ch], sr = br[ch];
    #pragma unroll
    for (int i = 0; i < 8; i++) {
        float xi = xv[i];
        sl += xi * Wl[ch * 8 + i];
        sr += xi * Wr[ch * 8 + i];
    }
    g_xl[idx] = sl;
    g_xr[idx] = sr;
}

// -------- 2. fused logits + exp + denom + unnormalized message scatter ------
__global__ void k_logits(const int* __restrict__ ei,
                         const float* __restrict__ ea,
                         const float* __restrict__ We,
                         const float* __restrict__ att, int E) {
    int warp = (blockIdx.x * blockDim.x + threadIdx.x) >> 5;
    int lane = threadIdx.x & 31;
    int e0 = warp * 4;
    if (e0 >= E) return;

    float4 at   = ((const float4*)att)[lane];
    float4 we01 = ((const float4*)We)[2 * lane];
    float4 we23 = ((const float4*)We)[2 * lane + 1];

    int src[4], dst[4];
    float2 eav[4];
    #pragma unroll
    for (int j = 0; j < 4; j++) {
        int e = min(e0 + j, E - 1);
        src[j] = ei[e];
        dst[j] = ei[E + e];
        eav[j] = ((const float2*)ea)[e];
    }
    float4 a[4], b[4];
    #pragma unroll
    for (int j = 0; j < 4; j++) a[j] = ((const float4*)g_xl)[src[j] * 32 + lane];
    #pragma unroll
    for (int j = 0; j < 4; j++) b[j] = ((const float4*)g_xr)[dst[j] * 32 + lane];

    float s[4];
    #pragma unroll
    for (int j = 0; j < 4; j++) {
        float e_0 = we01.x * eav[j].x + we01.y * eav[j].y;
        float e_1 = we01.z * eav[j].x + we01.w * eav[j].y;
        float e_2 = we23.x * eav[j].x + we23.y * eav[j].y;
        float e_3 = we23.z * eav[j].x + we23.w * eav[j].y;
        float z, acc = 0.f;
        z = a[j].x + b[j].x + e_0; z = z > 0.f ? z : NEG_SLOPE * z; acc += z * at.x;
        z = a[j].y + b[j].y + e_1; z = z > 0.f ? z : NEG_SLOPE * z; acc += z * at.y;
        z = a[j].z + b[j].z + e_2; z = z > 0.f ? z : NEG_SLOPE * z; acc += z * at.z;
        z = a[j].w + b[j].w + e_3; z = z > 0.f ? z : NEG_SLOPE * z; acc += z * at.w;
        s[j] = acc;
    }
    #pragma unroll
    for (int o = 8; o >= 1; o >>= 1) {
        #pragma unroll
        for (int j = 0; j < 4; j++)
            s[j] += __shfl_xor_sync(0xffffffffu, s[j], o, 16);
    }
    float p[4];
    #pragma unroll
    for (int j = 0; j < 4; j++) p[j] = __expf(s[j]);  // |logit| small: no max-sub

    if ((lane & 15) == 0) {
        int h = lane >> 4;
        #pragma unroll
        for (int j = 0; j < 4; j++) {
            int e = e0 + j;
            if (e < E) {
                g_expl[2 * e + h] = p[j];
                atomicAdd(&g_denom[2 * dst[j] + h], p[j]);
            }
        }
    }
    #pragma unroll
    for (int j = 0; j < 4; j++) {
        if (e0 + j < E) {
            float4 m = a[j];
            m.x *= p[j]; m.y *= p[j]; m.z *= p[j]; m.w *= p[j];
            red_add_v4(&g_hacc[dst[j] * HC + lane * 4], m);
        }
    }
}

// -------- 3. light alpha pass: alpha, ew, deg --------
__global__ void k_alpha(const int* __restrict__ ei,
                        float* __restrict__ alpha_out, int E) {
    int t = blockIdx.x * blockDim.x + threadIdx.x;
    int e0 = t * 2;
    if (e0 >= E) return;
    int e1 = min(e0 + 1, E - 1);
    int dst0 = ei[E + e0], dst1 = ei[E + e1];
    float2 p0 = ((const float2*)g_expl)[e0];
    float2 p1 = ((const float2*)g_expl)[e1];
    float2 d0 = ((const float2*)g_denom)[dst0];
    float2 d1 = ((const float2*)g_denom)[dst1];
    float a00 = __fdividef(p0.x, d0.x), a01 = __fdividef(p0.y, d0.y);
    float a10 = __fdividef(p1.x, d1.x), a11 = __fdividef(p1.y, d1.y);
    ((float2*)alpha_out)[e0] = make_float2(a00, a01);
    float ew0 = 0.5f * (a00 + a01);
    g_ew[e0] = ew0;
    atomicAdd(&g_deg[dst0], ew0);
    if (e0 + 1 < E) {
        ((float2*)alpha_out)[e1] = make_float2(a10, a11);
        float ew1 = 0.5f * (a10 + a11);
        g_ew[e1] = ew1;
        atomicAdd(&g_deg[dst1], ew1);
    }
}

// -------- 4. register-tiled node GEMM: 64 nodes/block, 4x4 tile/thread ------
// Two K-phases of 64 channels each to keep static smem < 48 KB.
// Wsh[k][col] and hsh[ch][node] padded to stride 68 (float4-aligned, 4-way
// STS conflicts on staging only). Inner loop: 2 LDS.128 -> 16 FFMA.
#define NHB 64
#define WP  68
__global__ void k_node_hw(const float* __restrict__ gat_bias,
                          const float* __restrict__ gcn_W, int N) {
    __shared__ __align__(16) float Wsh[64 * WP];   // 17.4 KB
    __shared__ __align__(16) float hsh[64 * WP];   // 17.4 KB
    __shared__ float inv0[NHB], inv1[NHB];
    __shared__ float bsh[HC];
    int t = threadIdx.x;                 // 256
    int base = blockIdx.x * NHB;

    if (t < HC) bsh[t] = gat_bias[t];
    if (t < NHB) {
        int n = base + t;
        if (n < N) {
            float2 dn = ((const float2*)g_denom)[n];
            inv0[t] = dn.x > 0.f ? __fdividef(1.f, dn.x) : 0.f;
            inv1[t] = dn.y > 0.f ? __fdividef(1.f, dn.y) : 0.f;
            float dg = g_deg[n];
            g_dinv[n] = dg > 0.f ? rsqrtf(dg) : 0.f;
        } else { inv0[t] = 0.f; inv1[t] = 0.f; }
    }
    __syncthreads();

    int tx = t & 15;          // col group: cols 4tx..4tx+3
    int ty = t >> 4;          // node group: nodes 4ty..4ty+3
    float acc[4][4];
    #pragma unroll
    for (int i = 0; i < 4; i++)
        #pragma unroll
        for (int j = 0; j < 4; j++) acc[i][j] = 0.f;

    #pragma unroll
    for (int ph = 0; ph < 2; ph++) {
        // stage W slice transposed: Wsh[k][c] = gcn_W[c*128 + ph*64 + k]
        {
            int k = t & 63, cb = t >> 6;
            #pragma unroll
            for (int j = 0; j < 16; j++) {
                int c = cb + j * 4;
                Wsh[k * WP + c] = gcn_W[c * HC + ph * 64 + k];
            }
        }
        // stage h slice: hsh[c][n] = relu(hacc*inv + bias)
        {
            int c = t & 63, nb = t >> 6;
            #pragma unroll
            for (int j = 0; j < 16; j++) {
                int nl = nb + j * 4;
                int n = base + nl;
                float v = 0.f;
                if (n < N) {
                    float iv = ph ? inv1[nl] : inv0[nl];
                    v = fmaxf(g_hacc[n * HC + ph * 64 + c] * iv + bsh[ph * 64 + c], 0.f);
                }
                hsh[c * WP + nl] = v;
            }
        }
        __syncthreads();
        #pragma unroll 4
        for (int k = 0; k < 64; k++) {
            float4 w = *(const float4*)&Wsh[k * WP + tx * 4];
            float4 h = *(const float4*)&hsh[k * WP + ty * 4];
            acc[0][0] += h.x * w.x; acc[0][1] += h.x * w.y;
            acc[0][2] += h.x * w.z; acc[0][3] += h.x * w.w;
            acc[1][0] += h.y * w.x; acc[1][1] += h.y * w.y;
            acc[1][2] += h.y * w.z; acc[1][3] += h.y * w.w;
            acc[2][0] += h.z * w.x; acc[2][1] += h.z * w.y;
            acc[2][2] += h.z * w.z; acc[2][3] += h.z * w.w;
            acc[3][0] += h.w * w.x; acc[3][1] += h.w * w.y;
            acc[3][2] += h.w * w.z; acc[3][3] += h.w * w.w;
        }
        __syncthreads();
    }
    #pragma unroll
    for (int i = 0; i < 4; i++) {
        int n = base + ty * 4 + i;
        if (n < N) {
            float4 o = make_float4(acc[i][0], acc[i][1], acc[i][2], acc[i][3]);
            ((float4*)g_hw)[n * 16 + tx] = o;
        }
    }
}

// -------- 5. GCN edge scatter: 16 lanes/edge, 8 edges per warp --------
__global__ void k_gcn_edge(const int* __restrict__ ei, int E) {
    int warp = (blockIdx.x * blockDim.x + threadIdx.x) >> 5;
    int lane = threadIdx.x & 31;
    int half = lane >> 4;
    int l    = lane & 15;
    int e0 = warp * 8 + half;
    if (e0 >= E) return;

    int src[4], dst[4];
    float nv[4];
    #pragma unroll
    for (int j = 0; j < 4; j++) {
        int e = min(e0 + 2 * j, E - 1);
        src[j] = ei[e];
        dst[j] = ei[E + e];
        nv[j]  = g_ew[e];
    }
    #pragma unroll
    for (int j = 0; j < 4; j++)
        nv[j] *= g_dinv[src[j]] * g_dinv[dst[j]];
    float4 v[4];
    #pragma unroll
    for (int j = 0; j < 4; j++)
        v[j] = ((const float4*)g_hw)[src[j] * 16 + l];
    #pragma unroll
    for (int j = 0; j < 4; j++) {
        if (e0 + 2 * j < E) {
            float4 m = v[j];
            m.x *= nv[j]; m.y *= nv[j]; m.z *= nv[j]; m.w *= nv[j];
            red_add_v4(&g_h2acc[dst[j] * HID + l * 4], m);
        }
    }
}

// -------- 6. per-node output --------
__global__ void k_node_out(const float* __restrict__ gcn_b,
                           const float* __restrict__ out_W,
                           const float* __restrict__ out_b,
                           float* __restrict__ out, int N) {
    int t = blockIdx.x * blockDim.x + threadIdx.x;
    int n = t >> 5;
    if (n >= N) return;
    int lane = t & 31;
    float2 hv = ((const float2*)g_h2acc)[n * 32 + lane];
    float h0 = fmaxf(hv.x + gcn_b[2 * lane],     0.f);
    float h1 = fmaxf(hv.y + gcn_b[2 * lane + 1], 0.f);
    float s0 = h0 * out_W[2 * lane]      + h1 * out_W[2 * lane + 1];
    float s1 = h0 * out_W[64 + 2 * lane] + h1 * out_W[64 + 2 * lane + 1];
    #pragma unroll
    for (int o = 16; o >= 1; o >>= 1) {
        s0 += __shfl_down_sync(0xffffffffu, s0, o);
        s1 += __shfl_down_sync(0xffffffffu, s1, o);
    }
    if (lane == 0) {
        out[2 * n]     = s0 + out_b[0];
        out[2 * n + 1] = s1 + out_b[1];
    }
}

extern "C" void kernel_launch(void* const* d_in, const int* in_sizes, int n_in,
                              void* d_out, int out_size) {
    const float* x        = (const float*)d_in[0];
    const float* ea       = (const float*)d_in[1];
    const int*   ei       = (const int*)d_in[2];   // int32 (JAX x64 disabled)
    const float* Wl       = (const float*)d_in[3];
    const float* bl       = (const float*)d_in[4];
    const float* Wr       = (const float*)d_in[5];
    const float* br       = (const float*)d_in[6];
    const float* We       = (const float*)d_in[7];
    const float* att      = (const float*)d_in[8];
    const float* gat_bias = (const float*)d_in[9];
    const float* gcn_W    = (const float*)d_in[10];
    const float* gcn_b    = (const float*)d_in[11];
    const float* out_W    = (const float*)d_in[12];
    const float* out_b    = (const float*)d_in[13];

    int N = in_sizes[0] / 8;     // IN=8
    int E = in_sizes[1] / 2;     // ED=2

    float* out       = (float*)d_out;
    float* alpha_out = (float*)d_out + (size_t)N * 2;

    const int NT = 256;
    int warpsL = (E + 3) / 4;   // 4 edges/warp
    int warpsG = (E + 7) / 8;   // 8 edges/warp
    k_proj<<<(N * HC + NT - 1) / NT, NT>>>(x, Wl, bl, Wr, br, N);
    k_logits<<<(int)(((size_t)warpsL * 32 + NT - 1) / NT), NT>>>(ei, ea, We, att, E);
    k_alpha<<<(E / 2 + NT - 1) / NT, NT>>>(ei, alpha_out, E);
    k_node_hw<<<(N + NHB - 1) / NHB, 256>>>(gat_bias, gcn_W, N);
    k_gcn_edge<<<(int)(((size_t)warpsG * 32 + NT - 1) / NT), NT>>>(ei, E);
    k_node_out<<<(int)(((size_t)N * 32 + NT - 1) / NT), NT>>>(gcn_b, out_W, out_b, out, N);
}